// round 1
// baseline (speedup 1.0000x reference)
#include <cuda_runtime.h>
#include <math.h>

#define S_LEN 2048
#define HID   2560
#define NH    32
#define NKV   8
#define HD    128

// Scratch (device globals; no allocation allowed)
__device__ float g_q  [S_LEN * NH  * HD];   // [s][h*128+d]
__device__ float g_k  [S_LEN * NKV * HD];   // [s][hk*128+d]
__device__ float g_v  [S_LEN * NKV * HD];   // [s][hk*128+d]
__device__ float g_att[S_LEN * NH  * HD];   // [s][h*128+d]

// ---------------------------------------------------------------------------
// GEMM: C[M,N] = A[M,K] @ B[N,K]^T   (both A and B are K-major row-major)
// BM=BN=128, BK=16, 256 threads, 8x8 per thread. All dims divisible.
// ---------------------------------------------------------------------------
__global__ __launch_bounds__(256) void gemm_nt(const float* __restrict__ A,
                                               const float* __restrict__ B,
                                               float* __restrict__ C,
                                               int M, int N, int K) {
    __shared__ float As[16][128];
    __shared__ float Bs[16][128];

    const int bx = blockIdx.x;     // N tile
    const int by = blockIdx.y;     // M tile
    const int tid = threadIdx.x;
    const int tx = tid & 15;       // 0..15
    const int ty = tid >> 4;       // 0..15

    const float* Ab = A + (size_t)by * 128 * K;
    const float* Bb = B + (size_t)bx * 128 * K;

    const int lrow = tid >> 2;          // 0..63
    const int lk4  = (tid & 3) * 4;     // 0,4,8,12

    float acc[8][8];
#pragma unroll
    for (int i = 0; i < 8; i++)
#pragma unroll
        for (int j = 0; j < 8; j++) acc[i][j] = 0.f;

    for (int k0 = 0; k0 < K; k0 += 16) {
#pragma unroll
        for (int half = 0; half < 2; half++) {
            int r = lrow + half * 64;
            float4 va = *(const float4*)(Ab + (size_t)r * K + k0 + lk4);
            As[lk4 + 0][r] = va.x; As[lk4 + 1][r] = va.y;
            As[lk4 + 2][r] = va.z; As[lk4 + 3][r] = va.w;
            float4 vb = *(const float4*)(Bb + (size_t)r * K + k0 + lk4);
            Bs[lk4 + 0][r] = vb.x; Bs[lk4 + 1][r] = vb.y;
            Bs[lk4 + 2][r] = vb.z; Bs[lk4 + 3][r] = vb.w;
        }
        __syncthreads();

#pragma unroll
        for (int k = 0; k < 16; k++) {
            float4 a0 = *(const float4*)&As[k][ty * 8];
            float4 a1 = *(const float4*)&As[k][ty * 8 + 4];
            float4 b0 = *(const float4*)&Bs[k][tx * 8];
            float4 b1 = *(const float4*)&Bs[k][tx * 8 + 4];
            float a[8] = {a0.x, a0.y, a0.z, a0.w, a1.x, a1.y, a1.z, a1.w};
            float b[8] = {b0.x, b0.y, b0.z, b0.w, b1.x, b1.y, b1.z, b1.w};
#pragma unroll
            for (int i = 0; i < 8; i++)
#pragma unroll
                for (int j = 0; j < 8; j++)
                    acc[i][j] += a[i] * b[j];
        }
        __syncthreads();
    }

#pragma unroll
    for (int i = 0; i < 8; i++) {
        float* crow = C + (size_t)(by * 128 + ty * 8 + i) * N + bx * 128 + tx * 8;
        *(float4*)(crow)     = make_float4(acc[i][0], acc[i][1], acc[i][2], acc[i][3]);
        *(float4*)(crow + 4) = make_float4(acc[i][4], acc[i][5], acc[i][6], acc[i][7]);
    }
}

// ---------------------------------------------------------------------------
// Fused RMSNorm + RoPE, in place. One block per (s, head), 128 threads.
// ---------------------------------------------------------------------------
__global__ __launch_bounds__(128) void rmsnorm_rope(float* __restrict__ data,
                                                    const float* __restrict__ w,
                                                    const float* __restrict__ cosp,
                                                    const float* __restrict__ sinp,
                                                    int nheads) {
    const int s = blockIdx.x;
    const int h = blockIdx.y;
    const int d = threadIdx.x;

    float* row = data + ((size_t)s * nheads + h) * HD;
    float x = row[d];

    float v = x * x;
#pragma unroll
    for (int o = 16; o > 0; o >>= 1) v += __shfl_xor_sync(0xffffffffu, v, o);

    __shared__ float warpsum[4];
    if ((d & 31) == 0) warpsum[d >> 5] = v;
    __syncthreads();
    float tot = warpsum[0] + warpsum[1] + warpsum[2] + warpsum[3];
    float r = rsqrtf(tot * (1.0f / HD) + 1e-6f);
    float nx = x * r * w[d];

    __shared__ float sh[HD];
    sh[d] = nx;
    __syncthreads();
    float partner = (d < 64) ? -sh[d + 64] : sh[d - 64];

    row[d] = nx * cosp[s * HD + d] + partner * sinp[s * HD + d];
}

// ---------------------------------------------------------------------------
// Causal flash attention, fp32. Block: 32 query rows, 128 threads
// (4 threads per row, each owns 32 of the 128 head dims). K-tiles of 32.
// ---------------------------------------------------------------------------
__global__ __launch_bounds__(128) void attention(const float* __restrict__ Q,
                                                 const float* __restrict__ K,
                                                 const float* __restrict__ V,
                                                 float* __restrict__ O) {
    __shared__ float Ks[32][132];   // padded rows: avoid 8-way store conflicts
    __shared__ float Vs[32][132];

    const int m0 = blockIdx.x * 32;
    const int h  = blockIdx.y;
    const int hk = h >> 2;               // GQA: 32 q heads -> 8 kv heads
    const int tid = threadIdx.x;
    const int r = tid >> 2;              // query row in tile
    const int p = tid & 3;               // dim-part (32 dims each)
    const int s = m0 + r;
    const float scale = 0.08838834764831845f;   // 128^-0.5

    float4 q4[8];
    const float4* qrow = (const float4*)(Q + ((size_t)s * NH + h) * HD + p * 32);
#pragma unroll
    for (int i = 0; i < 8; i++) q4[i] = qrow[i];

    float o[32];
#pragma unroll
    for (int i = 0; i < 32; i++) o[i] = 0.f;
    float mval = -INFINITY, l = 0.f;

    const int ntiles = m0 / 32 + 1;
    for (int t = 0; t < ntiles; t++) {
        const int n0 = t * 32;
        // load K,V tiles (each thread: one row j, 32 contiguous floats)
        {
            const int j  = tid >> 2;
            const int c0 = (tid & 3) * 32;
            const float4* ksrc = (const float4*)(K + ((size_t)(n0 + j) * NKV + hk) * HD + c0);
            const float4* vsrc = (const float4*)(V + ((size_t)(n0 + j) * NKV + hk) * HD + c0);
            float4* kd = (float4*)&Ks[j][c0];
            float4* vd = (float4*)&Vs[j][c0];
#pragma unroll
            for (int i = 0; i < 8; i++) { kd[i] = ksrc[i]; vd[i] = vsrc[i]; }
        }
        __syncthreads();

        float sc[32];
        float tmax = -INFINITY;
#pragma unroll
        for (int j = 0; j < 32; j++) {
            const float4* kr = (const float4*)&Ks[j][p * 32];
            float sum = 0.f;
#pragma unroll
            for (int i = 0; i < 8; i++) {
                float4 kv = kr[i];
                sum += kv.x * q4[i].x + kv.y * q4[i].y + kv.z * q4[i].z + kv.w * q4[i].w;
            }
            sum += __shfl_xor_sync(0xffffffffu, sum, 1);
            sum += __shfl_xor_sync(0xffffffffu, sum, 2);
            sum *= scale;
            if (n0 + j > s) sum = -INFINITY;   // causal mask
            sc[j] = sum;
            tmax = fmaxf(tmax, sum);
        }

        float mnew = fmaxf(mval, tmax);
        float corr = __expf(mval - mnew);
        float lsum = 0.f;
#pragma unroll
        for (int j = 0; j < 32; j++) { sc[j] = __expf(sc[j] - mnew); lsum += sc[j]; }
        l = l * corr + lsum;
        mval = mnew;
#pragma unroll
        for (int i = 0; i < 32; i++) o[i] *= corr;

#pragma unroll
        for (int j = 0; j < 32; j++) {
            float pj = sc[j];
            const float4* vr = (const float4*)&Vs[j][p * 32];
#pragma unroll
            for (int i = 0; i < 8; i++) {
                float4 vv = vr[i];
                o[4 * i + 0] += pj * vv.x;
                o[4 * i + 1] += pj * vv.y;
                o[4 * i + 2] += pj * vv.z;
                o[4 * i + 3] += pj * vv.w;
            }
        }
        __syncthreads();
    }

    const float inv = 1.f / l;
    float4* orow = (float4*)(O + ((size_t)s * NH + h) * HD + p * 32);
#pragma unroll
    for (int i = 0; i < 8; i++)
        orow[i] = make_float4(o[4 * i] * inv, o[4 * i + 1] * inv,
                              o[4 * i + 2] * inv, o[4 * i + 3] * inv);
}

// ---------------------------------------------------------------------------
extern "C" void kernel_launch(void* const* d_in, const int* in_sizes, int n_in,
                              void* d_out, int out_size) {
    const float* hs   = (const float*)d_in[0];   // (1,2048,2560)
    const float* cosp = (const float*)d_in[1];   // (1,2048,128)
    const float* sinp = (const float*)d_in[2];   // (1,2048,128)
    const float* Wq   = (const float*)d_in[3];   // (4096,2560)
    const float* Wk   = (const float*)d_in[4];   // (1024,2560)
    const float* Wv   = (const float*)d_in[5];   // (1024,2560)
    const float* Wo   = (const float*)d_in[6];   // (2560,4096)
    const float* qw   = (const float*)d_in[7];   // (128,)
    const float* kw   = (const float*)d_in[8];   // (128,)
    float* out = (float*)d_out;                  // (1,2048,2560)

    float *pq, *pk, *pv, *patt;
    cudaGetSymbolAddress((void**)&pq,   g_q);
    cudaGetSymbolAddress((void**)&pk,   g_k);
    cudaGetSymbolAddress((void**)&pv,   g_v);
    cudaGetSymbolAddress((void**)&patt, g_att);

    // Projections: C = X @ W^T
    gemm_nt<<<dim3((NH  * HD) / 128, S_LEN / 128), 256>>>(hs, Wq, pq, S_LEN, NH  * HD, HID);
    gemm_nt<<<dim3((NKV * HD) / 128, S_LEN / 128), 256>>>(hs, Wk, pk, S_LEN, NKV * HD, HID);
    gemm_nt<<<dim3((NKV * HD) / 128, S_LEN / 128), 256>>>(hs, Wv, pv, S_LEN, NKV * HD, HID);

    // RMSNorm + RoPE (in place)
    rmsnorm_rope<<<dim3(S_LEN, NH),  128>>>(pq, qw, cosp, sinp, NH);
    rmsnorm_rope<<<dim3(S_LEN, NKV), 128>>>(pk, kw, cosp, sinp, NKV);

    // Causal flash attention
    attention<<<dim3(S_LEN / 32, NH), 128>>>(pq, pk, pv, patt);

    // Output projection
    gemm_nt<<<dim3(HID / 128, S_LEN / 128), 256>>>(patt, Wo, out, S_LEN, HID, NH * HD);
}

// round 3
// speedup vs baseline: 1.1999x; 1.1999x over previous
#include <cuda_runtime.h>
#include <cuda_bf16.h>
#include <math.h>
#include <stdint.h>

#define S_LEN 2048
#define HID   2560
#define NH    32
#define NKV   8
#define HD    128
#define NQD   (NH*HD)    // 4096
#define NKD   (NKV*HD)   // 1024

// fp32 scratch
__device__ float g_q  [S_LEN * NQD];
__device__ float g_k  [S_LEN * NKD];
__device__ float g_v  [S_LEN * NKD];
__device__ float g_att[S_LEN * NQD];

// bf16 hi/lo split scratch
__device__ __nv_bfloat16 g_hs_h[S_LEN*HID], g_hs_l[S_LEN*HID];
__device__ __nv_bfloat16 g_wq_h[NQD*HID],  g_wq_l[NQD*HID];
__device__ __nv_bfloat16 g_wk_h[NKD*HID],  g_wk_l[NKD*HID];
__device__ __nv_bfloat16 g_wv_h[NKD*HID],  g_wv_l[NKD*HID];
__device__ __nv_bfloat16 g_wo_h[HID*NQD],  g_wo_l[HID*NQD];
__device__ __nv_bfloat16 g_at_h[S_LEN*NQD], g_at_l[S_LEN*NQD];

// ---------------------------------------------------------------------------
__device__ __forceinline__ uint32_t s2u(const void* p) {
    uint32_t a;
    asm("{ .reg .u64 t; cvta.to.shared.u64 t, %1; cvt.u32.u64 %0, t; }" : "=r"(a) : "l"(p));
    return a;
}
__device__ __forceinline__ void ldsm_x4(uint32_t* r, uint32_t addr) {
    asm volatile("ldmatrix.sync.aligned.m8n8.x4.shared.b16 {%0,%1,%2,%3}, [%4];"
                 : "=r"(r[0]), "=r"(r[1]), "=r"(r[2]), "=r"(r[3]) : "r"(addr));
}
__device__ __forceinline__ void mma16816(float* c, const uint32_t* a, const uint32_t* b) {
    asm volatile("mma.sync.aligned.m16n8k16.row.col.f32.bf16.bf16.f32 "
                 "{%0,%1,%2,%3}, {%4,%5,%6,%7}, {%8,%9}, {%0,%1,%2,%3};"
                 : "+f"(c[0]), "+f"(c[1]), "+f"(c[2]), "+f"(c[3])
                 : "r"(a[0]), "r"(a[1]), "r"(a[2]), "r"(a[3]), "r"(b[0]), "r"(b[1]));
}
__device__ __forceinline__ void cp16(uint32_t dst, const void* src) {
    asm volatile("cp.async.cg.shared.global [%0], [%1], 16;" :: "r"(dst), "l"(src));
}

// ---------------------------------------------------------------------------
// Split fp32 -> bf16 hi + bf16 lo
// ---------------------------------------------------------------------------
__global__ __launch_bounds__(256) void split_kernel(const float* __restrict__ x,
                                                    __nv_bfloat16* __restrict__ h,
                                                    __nv_bfloat16* __restrict__ l,
                                                    int n) {
    int i = blockIdx.x * blockDim.x + threadIdx.x;
    if (i < n) {
        float v = x[i];
        __nv_bfloat16 hb = __float2bfloat16(v);
        h[i] = hb;
        l[i] = __float2bfloat16(v - __bfloat162float(hb));
    }
}

// ---------------------------------------------------------------------------
// HMMA bf16-split GEMM: C[M,N] = (Ah+Al)[M,K] @ (Bh+Bl)[N,K]^T  (fp32 acc)
// 128x128 CTA tile, BK=32, 8 warps (2x4), warp tile 64x32, double-buffered
// cp.async smem, 80B row stride (conflict-free ldmatrix).
// ---------------------------------------------------------------------------
#define ROWB 80                       // bytes per smem row (32 bf16 + 8 pad)
#define TILE_BYTES  (128*ROWB)        // 10240
#define STAGE_BYTES (4*TILE_BYTES)    // 40960 (Ah, Al, Bh, Bl)
#define GEMM_DSM    (2*STAGE_BYTES + 128)

__global__ __launch_bounds__(256, 1) void gemm_tc(
    const __nv_bfloat16* __restrict__ Ah, const __nv_bfloat16* __restrict__ Al,
    const __nv_bfloat16* __restrict__ Bh, const __nv_bfloat16* __restrict__ Bl,
    float* __restrict__ C, int N, int K)
{
    extern __shared__ __align__(128) char sm_raw[];
    const uint32_t sbase = s2u(sm_raw);

    const int tid  = threadIdx.x;
    const int wid  = tid >> 5;
    const int lane = tid & 31;
    const int m0 = blockIdx.y * 128, n0 = blockIdx.x * 128;
    const int m0w = (wid >> 2) * 64, n0w = (wid & 3) * 32;

    const __nv_bfloat16* srcs[4] = {Ah, Al, Bh, Bl};

    auto load_stage = [&](int c, int st) {
        const int k0 = c * 32;
#pragma unroll
        for (int tl = 0; tl < 4; tl++) {
            const __nv_bfloat16* src = srcs[tl];
            const int rbase = (tl < 2) ? m0 : n0;
#pragma unroll
            for (int j = 0; j < 2; j++) {
                int chunk = tid + j * 256;          // 512 chunks per tile
                int row = chunk >> 2, cpos = chunk & 3;
                uint32_t dst = sbase + st * STAGE_BYTES + tl * TILE_BYTES
                             + row * ROWB + cpos * 16;
                cp16(dst, src + (size_t)(rbase + row) * K + k0 + cpos * 8);
            }
        }
        asm volatile("cp.async.commit_group;" ::: "memory");
    };

    float acc[4][4][4];
#pragma unroll
    for (int a = 0; a < 4; a++)
#pragma unroll
        for (int b = 0; b < 4; b++)
#pragma unroll
            for (int c = 0; c < 4; c++) acc[a][b][c] = 0.f;

    const int NC = K / 32;
    load_stage(0, 0);

    for (int c = 0; c < NC; c++) {
        const int st = c & 1;
        if (c + 1 < NC) {
            load_stage(c + 1, st ^ 1);
            asm volatile("cp.async.wait_group 1;" ::: "memory");
        } else {
            asm volatile("cp.async.wait_group 0;" ::: "memory");
        }
        __syncthreads();

        const uint32_t aBaseH = sbase + st * STAGE_BYTES;
        const uint32_t aBaseL = aBaseH + TILE_BYTES;
        const uint32_t bBaseH = aBaseH + 2 * TILE_BYTES;
        const uint32_t bBaseL = aBaseH + 3 * TILE_BYTES;

        const uint32_t aOffBase = (uint32_t)((m0w + (lane & 15)) * ROWB + (((lane >> 4) & 1) * 8) * 2);
        const uint32_t bOffBase = (uint32_t)((n0w + ((lane >> 1) & 8) + (lane & 7)) * ROWB + (lane & 8) * 2);

#pragma unroll
        for (int kk = 0; kk < 32; kk += 16) {
            uint32_t ah[4][4], al[4][4], bh[2][4], bl[2][4];
            const uint32_t aOff = aOffBase + kk * 2;
            const uint32_t bOff = bOffBase + kk * 2;
#pragma unroll
            for (int mt = 0; mt < 4; mt++) {
                ldsm_x4(ah[mt], aBaseH + aOff + mt * 16 * ROWB);
                ldsm_x4(al[mt], aBaseL + aOff + mt * 16 * ROWB);
            }
#pragma unroll
            for (int nt2 = 0; nt2 < 2; nt2++) {
                ldsm_x4(bh[nt2], bBaseH + bOff + nt2 * 16 * ROWB);
                ldsm_x4(bl[nt2], bBaseL + bOff + nt2 * 16 * ROWB);
            }
#pragma unroll
            for (int mt = 0; mt < 4; mt++)
#pragma unroll
                for (int nt = 0; nt < 4; nt++) {
                    const uint32_t* bhp = &bh[nt >> 1][(nt & 1) * 2];
                    const uint32_t* blp = &bl[nt >> 1][(nt & 1) * 2];
                    mma16816(acc[mt][nt], ah[mt], bhp);
                    mma16816(acc[mt][nt], ah[mt], blp);
                    mma16816(acc[mt][nt], al[mt], bhp);
                }
        }
        __syncthreads();
    }

    const int row0 = m0 + m0w + (lane >> 2);
    const int col0 = n0 + n0w + (lane & 3) * 2;
#pragma unroll
    for (int mt = 0; mt < 4; mt++)
#pragma unroll
        for (int nt = 0; nt < 4; nt++) {
            float* p0 = C + (size_t)(row0 + mt * 16) * N + col0 + nt * 8;
            *(float2*)p0 = make_float2(acc[mt][nt][0], acc[mt][nt][1]);
            float* p1 = p0 + 8 * (size_t)N;
            *(float2*)p1 = make_float2(acc[mt][nt][2], acc[mt][nt][3]);
        }
}

// ---------------------------------------------------------------------------
// Fused RMSNorm + RoPE, in place. One block per (s, head), 128 threads.
// ---------------------------------------------------------------------------
__global__ __launch_bounds__(128) void rmsnorm_rope(float* __restrict__ data,
                                                    const float* __restrict__ w,
                                                    const float* __restrict__ cosp,
                                                    const float* __restrict__ sinp,
                                                    int nheads) {
    const int s = blockIdx.x;
    const int h = blockIdx.y;
    const int d = threadIdx.x;

    float* row = data + ((size_t)s * nheads + h) * HD;
    float x = row[d];

    float v = x * x;
#pragma unroll
    for (int o = 16; o > 0; o >>= 1) v += __shfl_xor_sync(0xffffffffu, v, o);

    __shared__ float warpsum[4];
    if ((d & 31) == 0) warpsum[d >> 5] = v;
    __syncthreads();
    float tot = warpsum[0] + warpsum[1] + warpsum[2] + warpsum[3];
    float r = rsqrtf(tot * (1.0f / HD) + 1e-6f);
    float nx = x * r * w[d];

    __shared__ float sh[HD];
    sh[d] = nx;
    __syncthreads();
    float partner = (d < 64) ? -sh[d + 64] : sh[d - 64];

    row[d] = nx * cosp[s * HD + d] + partner * sinp[s * HD + d];
}

// ---------------------------------------------------------------------------
// Causal flash attention, fp32 SIMT.
// ---------------------------------------------------------------------------
__global__ __launch_bounds__(128) void attention(const float* __restrict__ Q,
                                                 const float* __restrict__ K,
                                                 const float* __restrict__ V,
                                                 float* __restrict__ O) {
    __shared__ float Ks[32][132];
    __shared__ float Vs[32][132];

    const int m0 = blockIdx.x * 32;
    const int h  = blockIdx.y;
    const int hk = h >> 2;
    const int tid = threadIdx.x;
    const int r = tid >> 2;
    const int p = tid & 3;
    const int s = m0 + r;
    const float scale = 0.08838834764831845f;

    float4 q4[8];
    const float4* qrow = (const float4*)(Q + ((size_t)s * NH + h) * HD + p * 32);
#pragma unroll
    for (int i = 0; i < 8; i++) q4[i] = qrow[i];

    float o[32];
#pragma unroll
    for (int i = 0; i < 32; i++) o[i] = 0.f;
    float mval = -INFINITY, l = 0.f;

    const int ntiles = m0 / 32 + 1;
    for (int t = 0; t < ntiles; t++) {
        const int n0 = t * 32;
        {
            const int j  = tid >> 2;
            const int c0 = (tid & 3) * 32;
            const float4* ksrc = (const float4*)(K + ((size_t)(n0 + j) * NKV + hk) * HD + c0);
            const float4* vsrc = (const float4*)(V + ((size_t)(n0 + j) * NKV + hk) * HD + c0);
            float4* kd = (float4*)&Ks[j][c0];
            float4* vd = (float4*)&Vs[j][c0];
#pragma unroll
            for (int i = 0; i < 8; i++) { kd[i] = ksrc[i]; vd[i] = vsrc[i]; }
        }
        __syncthreads();

        float sc[32];
        float tmax = -INFINITY;
#pragma unroll
        for (int j = 0; j < 32; j++) {
            const float4* kr = (const float4*)&Ks[j][p * 32];
            float sum = 0.f;
#pragma unroll
            for (int i = 0; i < 8; i++) {
                float4 kv = kr[i];
                sum += kv.x * q4[i].x + kv.y * q4[i].y + kv.z * q4[i].z + kv.w * q4[i].w;
            }
            sum += __shfl_xor_sync(0xffffffffu, sum, 1);
            sum += __shfl_xor_sync(0xffffffffu, sum, 2);
            sum *= scale;
            if (n0 + j > s) sum = -INFINITY;
            sc[j] = sum;
            tmax = fmaxf(tmax, sum);
        }

        float mnew = fmaxf(mval, tmax);
        float corr = __expf(mval - mnew);
        float lsum = 0.f;
#pragma unroll
        for (int j = 0; j < 32; j++) { sc[j] = __expf(sc[j] - mnew); lsum += sc[j]; }
        l = l * corr + lsum;
        mval = mnew;
#pragma unroll
        for (int i = 0; i < 32; i++) o[i] *= corr;

#pragma unroll
        for (int j = 0; j < 32; j++) {
            float pj = sc[j];
            const float4* vr = (const float4*)&Vs[j][p * 32];
#pragma unroll
            for (int i = 0; i < 8; i++) {
                float4 vv = vr[i];
                o[4 * i + 0] += pj * vv.x;
                o[4 * i + 1] += pj * vv.y;
                o[4 * i + 2] += pj * vv.z;
                o[4 * i + 3] += pj * vv.w;
            }
        }
        __syncthreads();
    }

    const float inv = 1.f / l;
    float4* orow = (float4*)(O + ((size_t)s * NH + h) * HD + p * 32);
#pragma unroll
    for (int i = 0; i < 8; i++)
        orow[i] = make_float4(o[4 * i] * inv, o[4 * i + 1] * inv,
                              o[4 * i + 2] * inv, o[4 * i + 3] * inv);
}

// ---------------------------------------------------------------------------
extern "C" void kernel_launch(void* const* d_in, const int* in_sizes, int n_in,
                              void* d_out, int out_size) {
    const float* hs   = (const float*)d_in[0];
    const float* cosp = (const float*)d_in[1];
    const float* sinp = (const float*)d_in[2];
    const float* Wq   = (const float*)d_in[3];
    const float* Wk   = (const float*)d_in[4];
    const float* Wv   = (const float*)d_in[5];
    const float* Wo   = (const float*)d_in[6];
    const float* qw   = (const float*)d_in[7];
    const float* kw   = (const float*)d_in[8];
    float* out = (float*)d_out;

    float *pq, *pk, *pv, *patt;
    cudaGetSymbolAddress((void**)&pq,   g_q);
    cudaGetSymbolAddress((void**)&pk,   g_k);
    cudaGetSymbolAddress((void**)&pv,   g_v);
    cudaGetSymbolAddress((void**)&patt, g_att);

    __nv_bfloat16 *hsh,*hsl,*wqh,*wql,*wkh,*wkl,*wvh,*wvl,*woh,*wol,*ath,*atl;
    cudaGetSymbolAddress((void**)&hsh, g_hs_h); cudaGetSymbolAddress((void**)&hsl, g_hs_l);
    cudaGetSymbolAddress((void**)&wqh, g_wq_h); cudaGetSymbolAddress((void**)&wql, g_wq_l);
    cudaGetSymbolAddress((void**)&wkh, g_wk_h); cudaGetSymbolAddress((void**)&wkl, g_wk_l);
    cudaGetSymbolAddress((void**)&wvh, g_wv_h); cudaGetSymbolAddress((void**)&wvl, g_wv_l);
    cudaGetSymbolAddress((void**)&woh, g_wo_h); cudaGetSymbolAddress((void**)&wol, g_wo_l);
    cudaGetSymbolAddress((void**)&ath, g_at_h); cudaGetSymbolAddress((void**)&atl, g_at_l);

    cudaFuncSetAttribute(gemm_tc, cudaFuncAttributeMaxDynamicSharedMemorySize, GEMM_DSM);

    // split inputs
    split_kernel<<<(S_LEN*HID + 255)/256, 256>>>(hs, hsh, hsl, S_LEN*HID);
    split_kernel<<<(NQD*HID + 255)/256, 256>>>(Wq, wqh, wql, NQD*HID);
    split_kernel<<<(NKD*HID + 255)/256, 256>>>(Wk, wkh, wkl, NKD*HID);
    split_kernel<<<(NKD*HID + 255)/256, 256>>>(Wv, wvh, wvl, NKD*HID);

    // projections (tensor cores, HMMA)
    gemm_tc<<<dim3(NQD/128, S_LEN/128), 256, GEMM_DSM>>>(hsh, hsl, wqh, wql, pq, NQD, HID);
    gemm_tc<<<dim3(NKD/128, S_LEN/128), 256, GEMM_DSM>>>(hsh, hsl, wkh, wkl, pk, NKD, HID);
    gemm_tc<<<dim3(NKD/128, S_LEN/128), 256, GEMM_DSM>>>(hsh, hsl, wvh, wvl, pv, NKD, HID);

    // RMSNorm + RoPE
    rmsnorm_rope<<<dim3(S_LEN, NH),  128>>>(pq, qw, cosp, sinp, NH);
    rmsnorm_rope<<<dim3(S_LEN, NKV), 128>>>(pk, kw, cosp, sinp, NKV);

    // causal flash attention (fp32 SIMT)
    attention<<<dim3(S_LEN / 32, NH), 128>>>(pq, pk, pv, patt);

    // output projection
    split_kernel<<<(S_LEN*NQD + 255)/256, 256>>>(patt, ath, atl, S_LEN*NQD);
    split_kernel<<<(HID*NQD + 255)/256, 256>>>(Wo, woh, wol, HID*NQD);
    gemm_tc<<<dim3(HID/128, S_LEN/128), 256, GEMM_DSM>>>(ath, atl, woh, wol, out, HID, NQD);
}

// round 4
// speedup vs baseline: 7.3716x; 6.1435x over previous
#include <cuda_runtime.h>
#include <cuda_bf16.h>
#include <math.h>
#include <stdint.h>

#define S_LEN 2048
#define HID   2560
#define NH    32
#define NKV   8
#define HD    128
#define NQD   (NH*HD)    // 4096
#define NKD   (NKV*HD)   // 1024

// fp32 GEMM outputs
__device__ float g_q[S_LEN * NQD];
__device__ float g_k[S_LEN * NKD];
__device__ float g_v[S_LEN * NKD];

// bf16 hi/lo scratch
__device__ __nv_bfloat16 g_hs_h[S_LEN*HID], g_hs_l[S_LEN*HID];
__device__ __nv_bfloat16 g_wq_h[NQD*HID],  g_wq_l[NQD*HID];
__device__ __nv_bfloat16 g_wk_h[NKD*HID],  g_wk_l[NKD*HID];
__device__ __nv_bfloat16 g_wv_h[NKD*HID],  g_wv_l[NKD*HID];
__device__ __nv_bfloat16 g_wo_h[HID*NQD],  g_wo_l[HID*NQD];
__device__ __nv_bfloat16 g_qh[S_LEN*NQD],  g_ql[S_LEN*NQD];
__device__ __nv_bfloat16 g_kh[S_LEN*NKD],  g_kl[S_LEN*NKD];
__device__ __nv_bfloat16 g_vh[S_LEN*NKD],  g_vl[S_LEN*NKD];
__device__ __nv_bfloat16 g_oh[S_LEN*NQD],  g_ol[S_LEN*NQD];

// ---------------------------------------------------------------------------
__device__ __forceinline__ uint32_t s2u(const void* p) {
    uint32_t a;
    asm("{ .reg .u64 t; cvta.to.shared.u64 t, %1; cvt.u32.u64 %0, t; }" : "=r"(a) : "l"(p));
    return a;
}
__device__ __forceinline__ void ldsm_x4(uint32_t* r, uint32_t addr) {
    asm volatile("ldmatrix.sync.aligned.m8n8.x4.shared.b16 {%0,%1,%2,%3}, [%4];"
                 : "=r"(r[0]), "=r"(r[1]), "=r"(r[2]), "=r"(r[3]) : "r"(addr));
}
__device__ __forceinline__ void ldsm_x4_t(uint32_t* r, uint32_t addr) {
    asm volatile("ldmatrix.sync.aligned.m8n8.x4.trans.shared.b16 {%0,%1,%2,%3}, [%4];"
                 : "=r"(r[0]), "=r"(r[1]), "=r"(r[2]), "=r"(r[3]) : "r"(addr));
}
__device__ __forceinline__ void mma16816(float* c, const uint32_t* a, const uint32_t* b) {
    asm volatile("mma.sync.aligned.m16n8k16.row.col.f32.bf16.bf16.f32 "
                 "{%0,%1,%2,%3}, {%4,%5,%6,%7}, {%8,%9}, {%0,%1,%2,%3};"
                 : "+f"(c[0]), "+f"(c[1]), "+f"(c[2]), "+f"(c[3])
                 : "r"(a[0]), "r"(a[1]), "r"(a[2]), "r"(a[3]), "r"(b[0]), "r"(b[1]));
}
__device__ __forceinline__ void cp16(uint32_t dst, const void* src) {
    asm volatile("cp.async.cg.shared.global [%0], [%1], 16;" :: "r"(dst), "l"(src));
}
__device__ __forceinline__ uint32_t pack_bf2(float x, float y) {
    __nv_bfloat162 t = __float22bfloat162_rn(make_float2(x, y));
    return *(uint32_t*)&t;
}
__device__ __forceinline__ float bf_lo(float x) {
    return x - __bfloat162float(__float2bfloat16(x));
}

// ---------------------------------------------------------------------------
__global__ __launch_bounds__(256) void split_kernel(const float* __restrict__ x,
                                                    __nv_bfloat16* __restrict__ h,
                                                    __nv_bfloat16* __restrict__ l,
                                                    int n) {
    int i = blockIdx.x * blockDim.x + threadIdx.x;
    if (i < n) {
        float v = x[i];
        __nv_bfloat16 hb = __float2bfloat16(v);
        h[i] = hb;
        l[i] = __float2bfloat16(v - __bfloat162float(hb));
    }
}

// ---------------------------------------------------------------------------
// HMMA bf16-split GEMM (unchanged from R3, passing)
// ---------------------------------------------------------------------------
#define ROWB 80
#define TILE_BYTES  (128*ROWB)
#define STAGE_BYTES (4*TILE_BYTES)
#define GEMM_DSM    (2*STAGE_BYTES + 128)

__global__ __launch_bounds__(256, 1) void gemm_tc(
    const __nv_bfloat16* __restrict__ Ah, const __nv_bfloat16* __restrict__ Al,
    const __nv_bfloat16* __restrict__ Bh, const __nv_bfloat16* __restrict__ Bl,
    float* __restrict__ C, int N, int K)
{
    extern __shared__ __align__(128) char sm_raw[];
    const uint32_t sbase = s2u(sm_raw);

    const int tid  = threadIdx.x;
    const int wid  = tid >> 5;
    const int lane = tid & 31;
    const int m0 = blockIdx.y * 128, n0 = blockIdx.x * 128;
    const int m0w = (wid >> 2) * 64, n0w = (wid & 3) * 32;

    const __nv_bfloat16* srcs[4] = {Ah, Al, Bh, Bl};

    auto load_stage = [&](int c, int st) {
        const int k0 = c * 32;
#pragma unroll
        for (int tl = 0; tl < 4; tl++) {
            const __nv_bfloat16* src = srcs[tl];
            const int rbase = (tl < 2) ? m0 : n0;
#pragma unroll
            for (int j = 0; j < 2; j++) {
                int chunk = tid + j * 256;
                int row = chunk >> 2, cpos = chunk & 3;
                uint32_t dst = sbase + st * STAGE_BYTES + tl * TILE_BYTES
                             + row * ROWB + cpos * 16;
                cp16(dst, src + (size_t)(rbase + row) * K + k0 + cpos * 8);
            }
        }
        asm volatile("cp.async.commit_group;" ::: "memory");
    };

    float acc[4][4][4];
#pragma unroll
    for (int a = 0; a < 4; a++)
#pragma unroll
        for (int b = 0; b < 4; b++)
#pragma unroll
            for (int c = 0; c < 4; c++) acc[a][b][c] = 0.f;

    const int NC = K / 32;
    load_stage(0, 0);

    for (int c = 0; c < NC; c++) {
        const int st = c & 1;
        if (c + 1 < NC) {
            load_stage(c + 1, st ^ 1);
            asm volatile("cp.async.wait_group 1;" ::: "memory");
        } else {
            asm volatile("cp.async.wait_group 0;" ::: "memory");
        }
        __syncthreads();

        const uint32_t aBaseH = sbase + st * STAGE_BYTES;
        const uint32_t aBaseL = aBaseH + TILE_BYTES;
        const uint32_t bBaseH = aBaseH + 2 * TILE_BYTES;
        const uint32_t bBaseL = aBaseH + 3 * TILE_BYTES;

        const uint32_t aOffBase = (uint32_t)((m0w + (lane & 15)) * ROWB + (((lane >> 4) & 1) * 8) * 2);
        const uint32_t bOffBase = (uint32_t)((n0w + ((lane >> 1) & 8) + (lane & 7)) * ROWB + (lane & 8) * 2);

#pragma unroll
        for (int kk = 0; kk < 32; kk += 16) {
            uint32_t ah[4][4], al[4][4], bh[2][4], bl[2][4];
            const uint32_t aOff = aOffBase + kk * 2;
            const uint32_t bOff = bOffBase + kk * 2;
#pragma unroll
            for (int mt = 0; mt < 4; mt++) {
                ldsm_x4(ah[mt], aBaseH + aOff + mt * 16 * ROWB);
                ldsm_x4(al[mt], aBaseL + aOff + mt * 16 * ROWB);
            }
#pragma unroll
            for (int nt2 = 0; nt2 < 2; nt2++) {
                ldsm_x4(bh[nt2], bBaseH + bOff + nt2 * 16 * ROWB);
                ldsm_x4(bl[nt2], bBaseL + bOff + nt2 * 16 * ROWB);
            }
#pragma unroll
            for (int mt = 0; mt < 4; mt++)
#pragma unroll
                for (int nt = 0; nt < 4; nt++) {
                    const uint32_t* bhp = &bh[nt >> 1][(nt & 1) * 2];
                    const uint32_t* blp = &bl[nt >> 1][(nt & 1) * 2];
                    mma16816(acc[mt][nt], ah[mt], bhp);
                    mma16816(acc[mt][nt], ah[mt], blp);
                    mma16816(acc[mt][nt], al[mt], bhp);
                }
        }
        __syncthreads();
    }

    const int row0 = m0 + m0w + (lane >> 2);
    const int col0 = n0 + n0w + (lane & 3) * 2;
#pragma unroll
    for (int mt = 0; mt < 4; mt++)
#pragma unroll
        for (int nt = 0; nt < 4; nt++) {
            float* p0 = C + (size_t)(row0 + mt * 16) * N + col0 + nt * 8;
            *(float2*)p0 = make_float2(acc[mt][nt][0], acc[mt][nt][1]);
            float* p1 = p0 + 8 * (size_t)N;
            *(float2*)p1 = make_float2(acc[mt][nt][2], acc[mt][nt][3]);
        }
}

// ---------------------------------------------------------------------------
// Fused RMSNorm + RoPE -> bf16 hi/lo. One block per (s, head), 128 threads.
// ---------------------------------------------------------------------------
__global__ __launch_bounds__(128) void rmsnorm_rope_split(
    const float* __restrict__ in, const float* __restrict__ w,
    const float* __restrict__ cosp, const float* __restrict__ sinp,
    int nheads, __nv_bfloat16* __restrict__ oh, __nv_bfloat16* __restrict__ ol)
{
    const int s = blockIdx.x;
    const int h = blockIdx.y;
    const int d = threadIdx.x;

    const size_t idx = ((size_t)s * nheads + h) * HD + d;
    float x = in[idx];

    float v = x * x;
#pragma unroll
    for (int o = 16; o > 0; o >>= 1) v += __shfl_xor_sync(0xffffffffu, v, o);

    __shared__ float warpsum[4];
    if ((d & 31) == 0) warpsum[d >> 5] = v;
    __syncthreads();
    float tot = warpsum[0] + warpsum[1] + warpsum[2] + warpsum[3];
    float r = rsqrtf(tot * (1.0f / HD) + 1e-6f);
    float nx = x * r * w[d];

    __shared__ float sh[HD];
    sh[d] = nx;
    __syncthreads();
    float partner = (d < 64) ? -sh[d + 64] : sh[d - 64];

    float y = nx * cosp[s * HD + d] + partner * sinp[s * HD + d];
    __nv_bfloat16 hb = __float2bfloat16(y);
    oh[idx] = hb;
    ol[idx] = __float2bfloat16(y - __bfloat162float(hb));
}

// ---------------------------------------------------------------------------
// HMMA flash attention with bf16 hi/lo splits.
// CTA: 128 queries x 1 head, 8 warps (16 rows each). KV tiles of 64.
// ---------------------------------------------------------------------------
#define AQ    128
#define AK    64
#define AROW  272                 // 128 bf16 + 16B pad
#define ATILE (64*AROW)           // 17408
#define ASTG  (4*ATILE)           // 69632 (Kh,Kl,Vh,Vl)
#define QTILE (128*AROW)          // 34816
#define ADSM  (2*ASTG)            // 139264

__global__ __launch_bounds__(256, 1) void attention_tc(
    const __nv_bfloat16* __restrict__ qh, const __nv_bfloat16* __restrict__ ql,
    const __nv_bfloat16* __restrict__ kh, const __nv_bfloat16* __restrict__ kl,
    const __nv_bfloat16* __restrict__ vh, const __nv_bfloat16* __restrict__ vl,
    __nv_bfloat16* __restrict__ oh, __nv_bfloat16* __restrict__ ol)
{
    extern __shared__ __align__(128) char sm_raw[];
    const uint32_t sbase = s2u(sm_raw);
    const int tid = threadIdx.x, wid = tid >> 5, lane = tid & 31;
    const int m0 = blockIdx.x * AQ;
    const int h = blockIdx.y, hk = h >> 2;
    const float scale = 0.08838834764831845f;

    // ---- stage Q (hi/lo) into smem, then registers
#pragma unroll
    for (int i = 0; i < 16; i++) {
        int c = tid + i * 256;
        int t = c >> 11;                 // 0=hi 1=lo (2048 chunks per tile)
        int row = (c >> 4) & 127, pos = c & 15;
        const __nv_bfloat16* src = t ? ql : qh;
        cp16(sbase + t * QTILE + row * AROW + pos * 16,
             src + ((size_t)(m0 + row) * NH + h) * HD + pos * 8);
    }
    asm volatile("cp.async.commit_group;" ::: "memory");
    asm volatile("cp.async.wait_group 0;" ::: "memory");
    __syncthreads();

    uint32_t qfh[8][4], qfl[8][4];
    {
        const uint32_t aOff = (uint32_t)((wid * 16 + (lane & 15)) * AROW + ((lane >> 4) & 1) * 16);
#pragma unroll
        for (int ks = 0; ks < 8; ks++) {
            ldsm_x4(qfh[ks], sbase + aOff + ks * 32);
            ldsm_x4(qfl[ks], sbase + QTILE + aOff + ks * 32);
        }
    }
    __syncthreads();   // all warps done before smem reuse

    auto load_kv = [&](int t, int st) {
        const int n0 = t * AK;
#pragma unroll
        for (int i = 0; i < 16; i++) {
            int c = tid + i * 256;
            int tl = c >> 10;            // 0..3
            int row = (c >> 4) & 63, pos = c & 15;
            const __nv_bfloat16* src = (tl == 0) ? kh : (tl == 1) ? kl : (tl == 2) ? vh : vl;
            cp16(sbase + st * ASTG + tl * ATILE + row * AROW + pos * 16,
                 src + ((size_t)(n0 + row) * NKV + hk) * HD + pos * 8);
        }
        asm volatile("cp.async.commit_group;" ::: "memory");
    };

    float out[16][4];
#pragma unroll
    for (int i = 0; i < 16; i++)
#pragma unroll
        for (int j = 0; j < 4; j++) out[i][j] = 0.f;
    float mlo = -INFINITY, mhi = -INFINITY, llo = 0.f, lhi = 0.f;

    const int row_lo = m0 + wid * 16 + (lane >> 2);
    const int row_hi = row_lo + 8;
    const int wlast  = m0 + wid * 16 + 15;

    const int NT = m0 / AK + 2;
    load_kv(0, 0);

    for (int t = 0; t < NT; t++) {
        const int st = t & 1;
        const int n0 = t * AK;
        if (t + 1 < NT) {
            load_kv(t + 1, st ^ 1);
            asm volatile("cp.async.wait_group 1;" ::: "memory");
        } else {
            asm volatile("cp.async.wait_group 0;" ::: "memory");
        }
        __syncthreads();

        if (n0 <= wlast) {
            const uint32_t Kh = sbase + st * ASTG;
            const uint32_t Kl = Kh + ATILE;
            const uint32_t Vh = Kh + 2 * ATILE;
            const uint32_t Vl = Kh + 3 * ATILE;

            // ---- QK^T
            float sc[8][4];
#pragma unroll
            for (int i = 0; i < 8; i++)
#pragma unroll
                for (int j = 0; j < 4; j++) sc[i][j] = 0.f;

            const uint32_t bOff = (uint32_t)((((lane >> 1) & 8) + (lane & 7)) * AROW + (lane & 8) * 2);
#pragma unroll
            for (int ks = 0; ks < 8; ks++) {
#pragma unroll
                for (int nt2 = 0; nt2 < 4; nt2++) {
                    uint32_t kbh[4], kbl[4];
                    uint32_t o = bOff + nt2 * 16 * AROW + ks * 32;
                    ldsm_x4(kbh, Kh + o);
                    ldsm_x4(kbl, Kl + o);
#pragma unroll
                    for (int half = 0; half < 2; half++) {
                        float* c = sc[2 * nt2 + half];
                        mma16816(c, qfh[ks], &kbh[half * 2]);
                        mma16816(c, qfh[ks], &kbl[half * 2]);
                        mma16816(c, qfl[ks], &kbh[half * 2]);
                    }
                }
            }

            // ---- scale + causal mask + online softmax
            float tmax0 = -INFINITY, tmax1 = -INFINITY;
#pragma unroll
            for (int nt = 0; nt < 8; nt++) {
                int colb = n0 + nt * 8 + (lane & 3) * 2;
#pragma unroll
                for (int j = 0; j < 4; j++) {
                    float v = sc[nt][j] * scale;
                    int col = colb + (j & 1);
                    int row = (j < 2) ? row_lo : row_hi;
                    if (col > row) v = -INFINITY;
                    sc[nt][j] = v;
                    if (j < 2) tmax0 = fmaxf(tmax0, v); else tmax1 = fmaxf(tmax1, v);
                }
            }
            tmax0 = fmaxf(tmax0, __shfl_xor_sync(0xffffffffu, tmax0, 1));
            tmax0 = fmaxf(tmax0, __shfl_xor_sync(0xffffffffu, tmax0, 2));
            tmax1 = fmaxf(tmax1, __shfl_xor_sync(0xffffffffu, tmax1, 1));
            tmax1 = fmaxf(tmax1, __shfl_xor_sync(0xffffffffu, tmax1, 2));

            float mn0 = fmaxf(mlo, tmax0), mn1 = fmaxf(mhi, tmax1);
            float c0 = __expf(mlo - mn0),  c1 = __expf(mhi - mn1);
            float s0 = 0.f, s1 = 0.f;
#pragma unroll
            for (int nt = 0; nt < 8; nt++) {
                float p0 = __expf(sc[nt][0] - mn0);
                float p1 = __expf(sc[nt][1] - mn0);
                float p2 = __expf(sc[nt][2] - mn1);
                float p3 = __expf(sc[nt][3] - mn1);
                sc[nt][0] = p0; sc[nt][1] = p1; sc[nt][2] = p2; sc[nt][3] = p3;
                s0 += p0 + p1; s1 += p2 + p3;
            }
            s0 += __shfl_xor_sync(0xffffffffu, s0, 1);
            s0 += __shfl_xor_sync(0xffffffffu, s0, 2);
            s1 += __shfl_xor_sync(0xffffffffu, s1, 1);
            s1 += __shfl_xor_sync(0xffffffffu, s1, 2);
            llo = llo * c0 + s0;  lhi = lhi * c1 + s1;
            mlo = mn0;  mhi = mn1;
#pragma unroll
            for (int nt = 0; nt < 16; nt++) {
                out[nt][0] *= c0; out[nt][1] *= c0;
                out[nt][2] *= c1; out[nt][3] *= c1;
            }

            // ---- P @ V
#pragma unroll
            for (int b = 0; b < 4; b++) {
                uint32_t ph[4], pl[4];
                ph[0] = pack_bf2(sc[2*b][0],   sc[2*b][1]);
                ph[1] = pack_bf2(sc[2*b][2],   sc[2*b][3]);
                ph[2] = pack_bf2(sc[2*b+1][0], sc[2*b+1][1]);
                ph[3] = pack_bf2(sc[2*b+1][2], sc[2*b+1][3]);
                pl[0] = pack_bf2(bf_lo(sc[2*b][0]),   bf_lo(sc[2*b][1]));
                pl[1] = pack_bf2(bf_lo(sc[2*b][2]),   bf_lo(sc[2*b][3]));
                pl[2] = pack_bf2(bf_lo(sc[2*b+1][0]), bf_lo(sc[2*b+1][1]));
                pl[3] = pack_bf2(bf_lo(sc[2*b+1][2]), bf_lo(sc[2*b+1][3]));

                const uint32_t vrow = (uint32_t)((b * 16 + (lane & 15)) * AROW + (lane >> 4) * 16);
#pragma unroll
                for (int nbp = 0; nbp < 8; nbp++) {
                    uint32_t vbh[4], vbl[4];
                    uint32_t o = vrow + nbp * 32;
                    ldsm_x4_t(vbh, Vh + o);
                    ldsm_x4_t(vbl, Vl + o);
#pragma unroll
                    for (int half = 0; half < 2; half++) {
                        float* c = out[2 * nbp + half];
                        mma16816(c, ph, &vbh[half * 2]);
                        mma16816(c, ph, &vbl[half * 2]);
                        mma16816(c, pl, &vbh[half * 2]);
                    }
                }
            }
        }
        __syncthreads();
    }

    // ---- epilogue: normalize, write bf16 hi/lo
    const float i0 = 1.f / llo, i1 = 1.f / lhi;
#pragma unroll
    for (int nt = 0; nt < 16; nt++) {
        int col = nt * 8 + (lane & 3) * 2;
        {
            float a = out[nt][0] * i0, b = out[nt][1] * i0;
            size_t idx = ((size_t)row_lo * NH + h) * HD + col;
            __nv_bfloat162 hv = __float22bfloat162_rn(make_float2(a, b));
            *(__nv_bfloat162*)(oh + idx) = hv;
            *(__nv_bfloat162*)(ol + idx) = __float22bfloat162_rn(
                make_float2(a - __bfloat162float(__low2bfloat16(hv)),
                            b - __bfloat162float(__high2bfloat16(hv))));
        }
        {
            float a = out[nt][2] * i1, b = out[nt][3] * i1;
            size_t idx = ((size_t)row_hi * NH + h) * HD + col;
            __nv_bfloat162 hv = __float22bfloat162_rn(make_float2(a, b));
            *(__nv_bfloat162*)(oh + idx) = hv;
            *(__nv_bfloat162*)(ol + idx) = __float22bfloat162_rn(
                make_float2(a - __bfloat162float(__low2bfloat16(hv)),
                            b - __bfloat162float(__high2bfloat16(hv))));
        }
    }
}

// ---------------------------------------------------------------------------
extern "C" void kernel_launch(void* const* d_in, const int* in_sizes, int n_in,
                              void* d_out, int out_size) {
    const float* hs   = (const float*)d_in[0];
    const float* cosp = (const float*)d_in[1];
    const float* sinp = (const float*)d_in[2];
    const float* Wq   = (const float*)d_in[3];
    const float* Wk   = (const float*)d_in[4];
    const float* Wv   = (const float*)d_in[5];
    const float* Wo   = (const float*)d_in[6];
    const float* qw   = (const float*)d_in[7];
    const float* kw   = (const float*)d_in[8];
    float* out = (float*)d_out;

    float *pq, *pk, *pv;
    cudaGetSymbolAddress((void**)&pq, g_q);
    cudaGetSymbolAddress((void**)&pk, g_k);
    cudaGetSymbolAddress((void**)&pv, g_v);

    __nv_bfloat16 *hsh,*hsl,*wqh,*wql,*wkh,*wkl,*wvh,*wvl,*woh,*wol;
    __nv_bfloat16 *qh,*ql,*kh,*kl,*vh,*vl,*ohp,*olp;
    cudaGetSymbolAddress((void**)&hsh, g_hs_h); cudaGetSymbolAddress((void**)&hsl, g_hs_l);
    cudaGetSymbolAddress((void**)&wqh, g_wq_h); cudaGetSymbolAddress((void**)&wql, g_wq_l);
    cudaGetSymbolAddress((void**)&wkh, g_wk_h); cudaGetSymbolAddress((void**)&wkl, g_wk_l);
    cudaGetSymbolAddress((void**)&wvh, g_wv_h); cudaGetSymbolAddress((void**)&wvl, g_wv_l);
    cudaGetSymbolAddress((void**)&woh, g_wo_h); cudaGetSymbolAddress((void**)&wol, g_wo_l);
    cudaGetSymbolAddress((void**)&qh, g_qh); cudaGetSymbolAddress((void**)&ql, g_ql);
    cudaGetSymbolAddress((void**)&kh, g_kh); cudaGetSymbolAddress((void**)&kl, g_kl);
    cudaGetSymbolAddress((void**)&vh, g_vh); cudaGetSymbolAddress((void**)&vl, g_vl);
    cudaGetSymbolAddress((void**)&ohp, g_oh); cudaGetSymbolAddress((void**)&olp, g_ol);

    cudaFuncSetAttribute(gemm_tc, cudaFuncAttributeMaxDynamicSharedMemorySize, GEMM_DSM);
    cudaFuncSetAttribute(attention_tc, cudaFuncAttributeMaxDynamicSharedMemorySize, ADSM);

    // splits
    split_kernel<<<(S_LEN*HID + 255)/256, 256>>>(hs, hsh, hsl, S_LEN*HID);
    split_kernel<<<(NQD*HID + 255)/256, 256>>>(Wq, wqh, wql, NQD*HID);
    split_kernel<<<(NKD*HID + 255)/256, 256>>>(Wk, wkh, wkl, NKD*HID);
    split_kernel<<<(NKD*HID + 255)/256, 256>>>(Wv, wvh, wvl, NKD*HID);
    split_kernel<<<(HID*NQD + 255)/256, 256>>>(Wo, woh, wol, HID*NQD);

    // projections
    gemm_tc<<<dim3(NQD/128, S_LEN/128), 256, GEMM_DSM>>>(hsh, hsl, wqh, wql, pq, NQD, HID);
    gemm_tc<<<dim3(NKD/128, S_LEN/128), 256, GEMM_DSM>>>(hsh, hsl, wkh, wkl, pk, NKD, HID);
    gemm_tc<<<dim3(NKD/128, S_LEN/128), 256, GEMM_DSM>>>(hsh, hsl, wvh, wvl, pv, NKD, HID);

    // rmsnorm+rope -> bf16 hi/lo ; v -> bf16 hi/lo
    rmsnorm_rope_split<<<dim3(S_LEN, NH),  128>>>(pq, qw, cosp, sinp, NH,  qh, ql);
    rmsnorm_rope_split<<<dim3(S_LEN, NKV), 128>>>(pk, kw, cosp, sinp, NKV, kh, kl);
    split_kernel<<<(S_LEN*NKD + 255)/256, 256>>>(pv, vh, vl, S_LEN*NKD);

    // flash attention (HMMA)
    attention_tc<<<dim3(S_LEN/AQ, NH), 256, ADSM>>>(qh, ql, kh, kl, vh, vl, ohp, olp);

    // output projection
    gemm_tc<<<dim3(HID/128, S_LEN/128), 256, GEMM_DSM>>>(ohp, olp, woh, wol, out, HID, NQD);
}

// round 5
// speedup vs baseline: 7.4151x; 1.0059x over previous
#include <cuda_runtime.h>
#include <cuda_bf16.h>
#include <math.h>
#include <stdint.h>

#define S_LEN 2048
#define HID   2560
#define NH    32
#define NKV   8
#define HD    128
#define NQD   (NH*HD)    // 4096
#define NKD   (NKV*HD)   // 1024
#define NQKV  (NQD+2*NKD) // 6144

// fp32 combined QKV GEMM output: [s][6144]  (q:0..4095, k:4096..5119, v:5120..6143)
__device__ float g_qkv[S_LEN * NQKV];

// bf16 hi/lo scratch
__device__ __nv_bfloat16 g_hs_h[S_LEN*HID], g_hs_l[S_LEN*HID];
__device__ __nv_bfloat16 g_w_h[NQKV*HID],  g_w_l[NQKV*HID];    // combined Wq|Wk|Wv
__device__ __nv_bfloat16 g_wo_h[HID*NQD],  g_wo_l[HID*NQD];
__device__ __nv_bfloat16 g_qh[S_LEN*NQD],  g_ql[S_LEN*NQD];
__device__ __nv_bfloat16 g_kh[S_LEN*NKD],  g_kl[S_LEN*NKD];
__device__ __nv_bfloat16 g_vh[S_LEN*NKD],  g_vl[S_LEN*NKD];
__device__ __nv_bfloat16 g_oh[S_LEN*NQD],  g_ol[S_LEN*NQD];

// ---------------------------------------------------------------------------
__device__ __forceinline__ uint32_t s2u(const void* p) {
    uint32_t a;
    asm("{ .reg .u64 t; cvta.to.shared.u64 t, %1; cvt.u32.u64 %0, t; }" : "=r"(a) : "l"(p));
    return a;
}
__device__ __forceinline__ void ldsm_x4(uint32_t* r, uint32_t addr) {
    asm volatile("ldmatrix.sync.aligned.m8n8.x4.shared.b16 {%0,%1,%2,%3}, [%4];"
                 : "=r"(r[0]), "=r"(r[1]), "=r"(r[2]), "=r"(r[3]) : "r"(addr));
}
__device__ __forceinline__ void ldsm_x4_t(uint32_t* r, uint32_t addr) {
    asm volatile("ldmatrix.sync.aligned.m8n8.x4.trans.shared.b16 {%0,%1,%2,%3}, [%4];"
                 : "=r"(r[0]), "=r"(r[1]), "=r"(r[2]), "=r"(r[3]) : "r"(addr));
}
__device__ __forceinline__ void mma16816(float* c, const uint32_t* a, const uint32_t* b) {
    asm volatile("mma.sync.aligned.m16n8k16.row.col.f32.bf16.bf16.f32 "
                 "{%0,%1,%2,%3}, {%4,%5,%6,%7}, {%8,%9}, {%0,%1,%2,%3};"
                 : "+f"(c[0]), "+f"(c[1]), "+f"(c[2]), "+f"(c[3])
                 : "r"(a[0]), "r"(a[1]), "r"(a[2]), "r"(a[3]), "r"(b[0]), "r"(b[1]));
}
__device__ __forceinline__ void cp16(uint32_t dst, const void* src) {
    asm volatile("cp.async.cg.shared.global [%0], [%1], 16;" :: "r"(dst), "l"(src));
}
__device__ __forceinline__ uint32_t pack_bf2(float x, float y) {
    __nv_bfloat162 t = __float22bfloat162_rn(make_float2(x, y));
    return *(uint32_t*)&t;
}
__device__ __forceinline__ float bf_lo(float x) {
    return x - __bfloat162float(__float2bfloat16(x));
}

// ---------------------------------------------------------------------------
__global__ __launch_bounds__(256) void split_kernel(const float* __restrict__ x,
                                                    __nv_bfloat16* __restrict__ h,
                                                    __nv_bfloat16* __restrict__ l,
                                                    int n) {
    int i = blockIdx.x * blockDim.x + threadIdx.x;
    if (i < n) {
        float v = x[i];
        __nv_bfloat16 hb = __float2bfloat16(v);
        h[i] = hb;
        l[i] = __float2bfloat16(v - __bfloat162float(hb));
    }
}

// strided split: src row stride, ncols contiguous per row
__global__ __launch_bounds__(256) void split_strided(const float* __restrict__ x,
                                                     int stride, int ncols,
                                                     __nv_bfloat16* __restrict__ h,
                                                     __nv_bfloat16* __restrict__ l,
                                                     int n) {
    int i = blockIdx.x * blockDim.x + threadIdx.x;
    if (i < n) {
        float v = x[(size_t)(i / ncols) * stride + (i % ncols)];
        __nv_bfloat16 hb = __float2bfloat16(v);
        h[i] = hb;
        l[i] = __float2bfloat16(v - __bfloat162float(hb));
    }
}

// ---------------------------------------------------------------------------
// HMMA bf16-split GEMM: C[M,N] = (Ah+Al)[M,K] @ (Bh+Bl)[N,K]^T  (fp32 acc)
// 128x128 CTA tile, BK=32, 8 warps, 4-stage cp.async pipeline, 1 sync/chunk.
// ---------------------------------------------------------------------------
#define ROWB 80
#define TILE_BYTES  (128*ROWB)        // 10240
#define STAGE_BYTES (4*TILE_BYTES)    // 40960
#define GSTG 4
#define GEMM_DSM    (GSTG*STAGE_BYTES)

__global__ __launch_bounds__(256, 1) void gemm_tc(
    const __nv_bfloat16* __restrict__ Ah, const __nv_bfloat16* __restrict__ Al,
    const __nv_bfloat16* __restrict__ Bh, const __nv_bfloat16* __restrict__ Bl,
    float* __restrict__ C, int N, int K)
{
    extern __shared__ __align__(128) char sm_raw[];
    const uint32_t sbase = s2u(sm_raw);

    const int tid  = threadIdx.x;
    const int wid  = tid >> 5;
    const int lane = tid & 31;
    const int m0 = blockIdx.y * 128, n0 = blockIdx.x * 128;
    const int m0w = (wid >> 2) * 64, n0w = (wid & 3) * 32;

    const __nv_bfloat16* srcs[4] = {Ah, Al, Bh, Bl};

    auto load_stage = [&](int c, int st) {
        const int k0 = c * 32;
#pragma unroll
        for (int tl = 0; tl < 4; tl++) {
            const __nv_bfloat16* src = srcs[tl];
            const int rbase = (tl < 2) ? m0 : n0;
#pragma unroll
            for (int j = 0; j < 2; j++) {
                int chunk = tid + j * 256;
                int row = chunk >> 2, cpos = chunk & 3;
                uint32_t dst = sbase + st * STAGE_BYTES + tl * TILE_BYTES
                             + row * ROWB + cpos * 16;
                cp16(dst, src + (size_t)(rbase + row) * K + k0 + cpos * 8);
            }
        }
        asm volatile("cp.async.commit_group;" ::: "memory");
    };

    float acc[4][4][4];
#pragma unroll
    for (int a = 0; a < 4; a++)
#pragma unroll
        for (int b = 0; b < 4; b++)
#pragma unroll
            for (int c = 0; c < 4; c++) acc[a][b][c] = 0.f;

    const int NC = K / 32;
    load_stage(0, 0);
    if (1 < NC) load_stage(1, 1);
    if (2 < NC) load_stage(2, 2);

    int st = 0;
    for (int c = 0; c < NC; c++) {
        const int rem = NC - 1 - c;         // loads still pending beyond c
        if (rem >= 2)      asm volatile("cp.async.wait_group 2;" ::: "memory");
        else if (rem == 1) asm volatile("cp.async.wait_group 1;" ::: "memory");
        else               asm volatile("cp.async.wait_group 0;" ::: "memory");
        __syncthreads();
        if (c + 3 < NC) {
            int st3 = st + 3; if (st3 >= GSTG) st3 -= GSTG;
            load_stage(c + 3, st3);
        }

        const uint32_t aBaseH = sbase + st * STAGE_BYTES;
        const uint32_t aBaseL = aBaseH + TILE_BYTES;
        const uint32_t bBaseH = aBaseH + 2 * TILE_BYTES;
        const uint32_t bBaseL = aBaseH + 3 * TILE_BYTES;

        const uint32_t aOffBase = (uint32_t)((m0w + (lane & 15)) * ROWB + (((lane >> 4) & 1) * 8) * 2);
        const uint32_t bOffBase = (uint32_t)((n0w + ((lane >> 1) & 8) + (lane & 7)) * ROWB + (lane & 8) * 2);

#pragma unroll
        for (int kk = 0; kk < 32; kk += 16) {
            uint32_t ah[4][4], al[4][4], bh[2][4], bl[2][4];
            const uint32_t aOff = aOffBase + kk * 2;
            const uint32_t bOff = bOffBase + kk * 2;
#pragma unroll
            for (int mt = 0; mt < 4; mt++) {
                ldsm_x4(ah[mt], aBaseH + aOff + mt * 16 * ROWB);
                ldsm_x4(al[mt], aBaseL + aOff + mt * 16 * ROWB);
            }
#pragma unroll
            for (int nt2 = 0; nt2 < 2; nt2++) {
                ldsm_x4(bh[nt2], bBaseH + bOff + nt2 * 16 * ROWB);
                ldsm_x4(bl[nt2], bBaseL + bOff + nt2 * 16 * ROWB);
            }
#pragma unroll
            for (int mt = 0; mt < 4; mt++)
#pragma unroll
                for (int nt = 0; nt < 4; nt++) {
                    const uint32_t* bhp = &bh[nt >> 1][(nt & 1) * 2];
                    const uint32_t* blp = &bl[nt >> 1][(nt & 1) * 2];
                    mma16816(acc[mt][nt], ah[mt], bhp);
                    mma16816(acc[mt][nt], ah[mt], blp);
                    mma16816(acc[mt][nt], al[mt], bhp);
                }
        }
        if (++st == GSTG) st = 0;
    }

    const int row0 = m0 + m0w + (lane >> 2);
    const int col0 = n0 + n0w + (lane & 3) * 2;
#pragma unroll
    for (int mt = 0; mt < 4; mt++)
#pragma unroll
        for (int nt = 0; nt < 4; nt++) {
            float* p0 = C + (size_t)(row0 + mt * 16) * N + col0 + nt * 8;
            *(float2*)p0 = make_float2(acc[mt][nt][0], acc[mt][nt][1]);
            float* p1 = p0 + 8 * (size_t)N;
            *(float2*)p1 = make_float2(acc[mt][nt][2], acc[mt][nt][3]);
        }
}

// ---------------------------------------------------------------------------
// Fused RMSNorm + RoPE -> bf16 hi/lo. Strided fp32 input (combined QKV buf).
// ---------------------------------------------------------------------------
__global__ __launch_bounds__(128) void rmsnorm_rope_split(
    const float* __restrict__ in, int in_stride, const float* __restrict__ w,
    const float* __restrict__ cosp, const float* __restrict__ sinp,
    int nheads, __nv_bfloat16* __restrict__ oh, __nv_bfloat16* __restrict__ ol)
{
    const int s = blockIdx.x;
    const int h = blockIdx.y;
    const int d = threadIdx.x;

    float x = in[(size_t)s * in_stride + h * HD + d];

    float v = x * x;
#pragma unroll
    for (int o = 16; o > 0; o >>= 1) v += __shfl_xor_sync(0xffffffffu, v, o);

    __shared__ float warpsum[4];
    if ((d & 31) == 0) warpsum[d >> 5] = v;
    __syncthreads();
    float tot = warpsum[0] + warpsum[1] + warpsum[2] + warpsum[3];
    float r = rsqrtf(tot * (1.0f / HD) + 1e-6f);
    float nx = x * r * w[d];

    __shared__ float sh[HD];
    sh[d] = nx;
    __syncthreads();
    float partner = (d < 64) ? -sh[d + 64] : sh[d - 64];

    float y = nx * cosp[s * HD + d] + partner * sinp[s * HD + d];
    __nv_bfloat16 hb = __float2bfloat16(y);
    const size_t idx = ((size_t)s * nheads + h) * HD + d;
    oh[idx] = hb;
    ol[idx] = __float2bfloat16(y - __bfloat162float(hb));
}

// ---------------------------------------------------------------------------
// HMMA flash attention, bf16 hi/lo, 3-stage cp.async pipeline, 1 sync/tile.
// CTA: 128 queries x 1 head, 8 warps. KV tiles of 64.
// ---------------------------------------------------------------------------
#define AQ    128
#define AK    64
#define AROW  272
#define ATILE (64*AROW)           // 17408
#define ASTG  (4*ATILE)           // 69632
#define QTILE (128*AROW)          // 34816
#define NSTG  3
#define ADSM  (NSTG*ASTG)         // 208896

__global__ __launch_bounds__(256, 1) void attention_tc(
    const __nv_bfloat16* __restrict__ qh, const __nv_bfloat16* __restrict__ ql,
    const __nv_bfloat16* __restrict__ kh, const __nv_bfloat16* __restrict__ kl,
    const __nv_bfloat16* __restrict__ vh, const __nv_bfloat16* __restrict__ vl,
    __nv_bfloat16* __restrict__ oh, __nv_bfloat16* __restrict__ ol)
{
    extern __shared__ __align__(128) char sm_raw[];
    const uint32_t sbase = s2u(sm_raw);
    const int tid = threadIdx.x, wid = tid >> 5, lane = tid & 31;
    const int m0 = blockIdx.x * AQ;
    const int h = blockIdx.y, hk = h >> 2;
    const float scale = 0.08838834764831845f;

    // ---- stage Q (hi/lo) into smem (stage-0 region), then registers
#pragma unroll
    for (int i = 0; i < 16; i++) {
        int c = tid + i * 256;
        int t = c >> 11;
        int row = (c >> 4) & 127, pos = c & 15;
        const __nv_bfloat16* src = t ? ql : qh;
        cp16(sbase + t * QTILE + row * AROW + pos * 16,
             src + ((size_t)(m0 + row) * NH + h) * HD + pos * 8);
    }
    asm volatile("cp.async.commit_group;" ::: "memory");
    asm volatile("cp.async.wait_group 0;" ::: "memory");
    __syncthreads();

    uint32_t qfh[8][4], qfl[8][4];
    {
        const uint32_t aOff = (uint32_t)((wid * 16 + (lane & 15)) * AROW + ((lane >> 4) & 1) * 16);
#pragma unroll
        for (int ks = 0; ks < 8; ks++) {
            ldsm_x4(qfh[ks], sbase + aOff + ks * 32);
            ldsm_x4(qfl[ks], sbase + QTILE + aOff + ks * 32);
        }
    }
    __syncthreads();

    auto load_kv = [&](int t, int st) {
        const int n0 = t * AK;
#pragma unroll
        for (int i = 0; i < 16; i++) {
            int c = tid + i * 256;
            int tl = c >> 10;
            int row = (c >> 4) & 63, pos = c & 15;
            const __nv_bfloat16* src = (tl == 0) ? kh : (tl == 1) ? kl : (tl == 2) ? vh : vl;
            cp16(sbase + st * ASTG + tl * ATILE + row * AROW + pos * 16,
                 src + ((size_t)(n0 + row) * NKV + hk) * HD + pos * 8);
        }
        asm volatile("cp.async.commit_group;" ::: "memory");
    };

    float out[16][4];
#pragma unroll
    for (int i = 0; i < 16; i++)
#pragma unroll
        for (int j = 0; j < 4; j++) out[i][j] = 0.f;
    float mlo = -INFINITY, mhi = -INFINITY, llo = 0.f, lhi = 0.f;

    const int row_lo = m0 + wid * 16 + (lane >> 2);
    const int row_hi = row_lo + 8;
    const int wlast  = m0 + wid * 16 + 15;

    const int NT = m0 / AK + 2;
    load_kv(0, 0);
    if (1 < NT) load_kv(1, 1);

    int st = 0;
    for (int t = 0; t < NT; t++) {
        const int n0 = t * AK;
        const int rem = NT - 1 - t;
        if (rem >= 1) asm volatile("cp.async.wait_group 1;" ::: "memory");
        else          asm volatile("cp.async.wait_group 0;" ::: "memory");
        __syncthreads();
        if (t + 2 < NT) {
            int st2 = st + 2; if (st2 >= NSTG) st2 -= NSTG;
            load_kv(t + 2, st2);
        }

        if (n0 <= wlast) {
            const uint32_t Kh = sbase + st * ASTG;
            const uint32_t Kl = Kh + ATILE;
            const uint32_t Vh = Kh + 2 * ATILE;
            const uint32_t Vl = Kh + 3 * ATILE;

            // ---- QK^T
            float sc[8][4];
#pragma unroll
            for (int i = 0; i < 8; i++)
#pragma unroll
                for (int j = 0; j < 4; j++) sc[i][j] = 0.f;

            const uint32_t bOff = (uint32_t)((((lane >> 1) & 8) + (lane & 7)) * AROW + (lane & 8) * 2);
#pragma unroll
            for (int ks = 0; ks < 8; ks++) {
#pragma unroll
                for (int nt2 = 0; nt2 < 4; nt2++) {
                    uint32_t kbh[4], kbl[4];
                    uint32_t o = bOff + nt2 * 16 * AROW + ks * 32;
                    ldsm_x4(kbh, Kh + o);
                    ldsm_x4(kbl, Kl + o);
#pragma unroll
                    for (int half = 0; half < 2; half++) {
                        float* c = sc[2 * nt2 + half];
                        mma16816(c, qfh[ks], &kbh[half * 2]);
                        mma16816(c, qfh[ks], &kbl[half * 2]);
                        mma16816(c, qfl[ks], &kbh[half * 2]);
                    }
                }
            }

            // ---- scale + causal mask + online softmax
            float tmax0 = -INFINITY, tmax1 = -INFINITY;
#pragma unroll
            for (int nt = 0; nt < 8; nt++) {
                int colb = n0 + nt * 8 + (lane & 3) * 2;
#pragma unroll
                for (int j = 0; j < 4; j++) {
                    float v = sc[nt][j] * scale;
                    int col = colb + (j & 1);
                    int row = (j < 2) ? row_lo : row_hi;
                    if (col > row) v = -INFINITY;
                    sc[nt][j] = v;
                    if (j < 2) tmax0 = fmaxf(tmax0, v); else tmax1 = fmaxf(tmax1, v);
                }
            }
            tmax0 = fmaxf(tmax0, __shfl_xor_sync(0xffffffffu, tmax0, 1));
            tmax0 = fmaxf(tmax0, __shfl_xor_sync(0xffffffffu, tmax0, 2));
            tmax1 = fmaxf(tmax1, __shfl_xor_sync(0xffffffffu, tmax1, 1));
            tmax1 = fmaxf(tmax1, __shfl_xor_sync(0xffffffffu, tmax1, 2));

            float mn0 = fmaxf(mlo, tmax0), mn1 = fmaxf(mhi, tmax1);
            float c0 = __expf(mlo - mn0),  c1 = __expf(mhi - mn1);
            float s0 = 0.f, s1 = 0.f;
#pragma unroll
            for (int nt = 0; nt < 8; nt++) {
                float p0 = __expf(sc[nt][0] - mn0);
                float p1 = __expf(sc[nt][1] - mn0);
                float p2 = __expf(sc[nt][2] - mn1);
                float p3 = __expf(sc[nt][3] - mn1);
                sc[nt][0] = p0; sc[nt][1] = p1; sc[nt][2] = p2; sc[nt][3] = p3;
                s0 += p0 + p1; s1 += p2 + p3;
            }
            s0 += __shfl_xor_sync(0xffffffffu, s0, 1);
            s0 += __shfl_xor_sync(0xffffffffu, s0, 2);
            s1 += __shfl_xor_sync(0xffffffffu, s1, 1);
            s1 += __shfl_xor_sync(0xffffffffu, s1, 2);
            llo = llo * c0 + s0;  lhi = lhi * c1 + s1;
            mlo = mn0;  mhi = mn1;
#pragma unroll
            for (int nt = 0; nt < 16; nt++) {
                out[nt][0] *= c0; out[nt][1] *= c0;
                out[nt][2] *= c1; out[nt][3] *= c1;
            }

            // ---- P @ V
#pragma unroll
            for (int b = 0; b < 4; b++) {
                uint32_t ph[4], pl[4];
                ph[0] = pack_bf2(sc[2*b][0],   sc[2*b][1]);
                ph[1] = pack_bf2(sc[2*b][2],   sc[2*b][3]);
                ph[2] = pack_bf2(sc[2*b+1][0], sc[2*b+1][1]);
                ph[3] = pack_bf2(sc[2*b+1][2], sc[2*b+1][3]);
                pl[0] = pack_bf2(bf_lo(sc[2*b][0]),   bf_lo(sc[2*b][1]));
                pl[1] = pack_bf2(bf_lo(sc[2*b][2]),   bf_lo(sc[2*b][3]));
                pl[2] = pack_bf2(bf_lo(sc[2*b+1][0]), bf_lo(sc[2*b+1][1]));
                pl[3] = pack_bf2(bf_lo(sc[2*b+1][2]), bf_lo(sc[2*b+1][3]));

                const uint32_t vrow = (uint32_t)((b * 16 + (lane & 15)) * AROW + (lane >> 4) * 16);
#pragma unroll
                for (int nbp = 0; nbp < 8; nbp++) {
                    uint32_t vbh[4], vbl[4];
                    uint32_t o = vrow + nbp * 32;
                    ldsm_x4_t(vbh, Vh + o);
                    ldsm_x4_t(vbl, Vl + o);
#pragma unroll
                    for (int half = 0; half < 2; half++) {
                        float* c = out[2 * nbp + half];
                        mma16816(c, ph, &vbh[half * 2]);
                        mma16816(c, ph, &vbl[half * 2]);
                        mma16816(c, pl, &vbh[half * 2]);
                    }
                }
            }
        }
        if (++st == NSTG) st = 0;
    }

    // ---- epilogue: normalize, write bf16 hi/lo
    const float i0 = 1.f / llo, i1 = 1.f / lhi;
#pragma unroll
    for (int nt = 0; nt < 16; nt++) {
        int col = nt * 8 + (lane & 3) * 2;
        {
            float a = out[nt][0] * i0, b = out[nt][1] * i0;
            size_t idx = ((size_t)row_lo * NH + h) * HD + col;
            __nv_bfloat162 hv = __float22bfloat162_rn(make_float2(a, b));
            *(__nv_bfloat162*)(oh + idx) = hv;
            *(__nv_bfloat162*)(ol + idx) = __float22bfloat162_rn(
                make_float2(a - __bfloat162float(__low2bfloat16(hv)),
                            b - __bfloat162float(__high2bfloat16(hv))));
        }
        {
            float a = out[nt][2] * i1, b = out[nt][3] * i1;
            size_t idx = ((size_t)row_hi * NH + h) * HD + col;
            __nv_bfloat162 hv = __float22bfloat162_rn(make_float2(a, b));
            *(__nv_bfloat162*)(oh + idx) = hv;
            *(__nv_bfloat162*)(ol + idx) = __float22bfloat162_rn(
                make_float2(a - __bfloat162float(__low2bfloat16(hv)),
                            b - __bfloat162float(__high2bfloat16(hv))));
        }
    }
}

// ---------------------------------------------------------------------------
extern "C" void kernel_launch(void* const* d_in, const int* in_sizes, int n_in,
                              void* d_out, int out_size) {
    const float* hs   = (const float*)d_in[0];
    const float* cosp = (const float*)d_in[1];
    const float* sinp = (const float*)d_in[2];
    const float* Wq   = (const float*)d_in[3];
    const float* Wk   = (const float*)d_in[4];
    const float* Wv   = (const float*)d_in[5];
    const float* Wo   = (const float*)d_in[6];
    const float* qw   = (const float*)d_in[7];
    const float* kw   = (const float*)d_in[8];
    float* out = (float*)d_out;

    float* pqkv;
    cudaGetSymbolAddress((void**)&pqkv, g_qkv);

    __nv_bfloat16 *hsh,*hsl,*wh,*wl,*woh,*wol;
    __nv_bfloat16 *qh,*ql,*kh,*kl,*vh,*vl,*ohp,*olp;
    cudaGetSymbolAddress((void**)&hsh, g_hs_h); cudaGetSymbolAddress((void**)&hsl, g_hs_l);
    cudaGetSymbolAddress((void**)&wh,  g_w_h);  cudaGetSymbolAddress((void**)&wl,  g_w_l);
    cudaGetSymbolAddress((void**)&woh, g_wo_h); cudaGetSymbolAddress((void**)&wol, g_wo_l);
    cudaGetSymbolAddress((void**)&qh, g_qh); cudaGetSymbolAddress((void**)&ql, g_ql);
    cudaGetSymbolAddress((void**)&kh, g_kh); cudaGetSymbolAddress((void**)&kl, g_kl);
    cudaGetSymbolAddress((void**)&vh, g_vh); cudaGetSymbolAddress((void**)&vl, g_vl);
    cudaGetSymbolAddress((void**)&ohp, g_oh); cudaGetSymbolAddress((void**)&olp, g_ol);

    cudaFuncSetAttribute(gemm_tc, cudaFuncAttributeMaxDynamicSharedMemorySize, GEMM_DSM);
    cudaFuncSetAttribute(attention_tc, cudaFuncAttributeMaxDynamicSharedMemorySize, ADSM);

    // splits: hs, combined W (Wq|Wk|Wv), Wo
    split_kernel<<<(S_LEN*HID + 255)/256, 256>>>(hs, hsh, hsl, S_LEN*HID);
    split_kernel<<<(NQD*HID + 255)/256, 256>>>(Wq, wh,              wl,              NQD*HID);
    split_kernel<<<(NKD*HID + 255)/256, 256>>>(Wk, wh + (size_t)NQD*HID, wl + (size_t)NQD*HID, NKD*HID);
    split_kernel<<<(NKD*HID + 255)/256, 256>>>(Wv, wh + (size_t)(NQD+NKD)*HID, wl + (size_t)(NQD+NKD)*HID, NKD*HID);
    split_kernel<<<(HID*NQD + 255)/256, 256>>>(Wo, woh, wol, HID*NQD);

    // fused QKV projection: [2048, 6144]
    gemm_tc<<<dim3(NQKV/128, S_LEN/128), 256, GEMM_DSM>>>(hsh, hsl, wh, wl, pqkv, NQKV, HID);

    // rmsnorm+rope -> bf16 hi/lo (strided reads from combined buffer)
    rmsnorm_rope_split<<<dim3(S_LEN, NH),  128>>>(pqkv,        NQKV, qw, cosp, sinp, NH,  qh, ql);
    rmsnorm_rope_split<<<dim3(S_LEN, NKV), 128>>>(pqkv + NQD,  NQKV, kw, cosp, sinp, NKV, kh, kl);
    split_strided<<<(S_LEN*NKD + 255)/256, 256>>>(pqkv + NQD + NKD, NQKV, NKD, vh, vl, S_LEN*NKD);

    // flash attention (HMMA)
    attention_tc<<<dim3(S_LEN/AQ, NH), 256, ADSM>>>(qh, ql, kh, kl, vh, vl, ohp, olp);

    // output projection
    gemm_tc<<<dim3(HID/128, S_LEN/128), 256, GEMM_DSM>>>(ohp, olp, woh, wol, out, HID, NQD);
}